// round 2
// baseline (speedup 1.0000x reference)
#include <cuda_runtime.h>
#include <cstdint>
#include <cstddef>

#define T_DIM  32
#define K2     512
#define KD     262144           // 1*64*4096 fan-in
#define THRESH 0.2f

#define NSPLIT 222              // K splits -> grid 444 = 148 SMs * 3 blocks
#define KS     8                // k per slab
#define NSLAB_TOT (KD / KS)     // 32768
#define SLAB_BASE (NSLAB_TOT / NSPLIT)            // 147
#define SLAB_REM  (NSLAB_TOT - SLAB_BASE * NSPLIT) // 134
#define OTILE  256
#define WST    256              // ws row stride (floats)
#define RST    64               // rs row stride (floats), rec duplicated

// scratch (device globals: no allocations allowed)
__device__ float g_partial[(size_t)NSPLIT * T_DIM * K2];  // [sp][t][o], ~14.5MB
__device__ float g_dot[T_DIM * K2];                       // [t][o]

__device__ __forceinline__ void fma2(unsigned long long& d,
                                     unsigned long long a,
                                     unsigned long long b) {
    asm("fma.rn.f32x2 %0, %1, %2, %0;" : "+l"(d) : "l"(a), "l"(b));
}
__device__ __forceinline__ unsigned long long dup2(float w) {
    unsigned long long r;
    asm("mov.b64 %0, {%1, %1};" : "=l"(r) : "f"(w));
    return r;
}

// ---------------------------------------------------------------------------
// GEMM: partial[sp][t][o] = sum_{k in split sp} rec[t][k] * w[o][k]
// block: 256 threads, tile 256 o x 32 t, per-thread 8 o (4 f32x2 pairs) x 4 t
// double-buffered smem, register prefetch of next slab
// ---------------------------------------------------------------------------
__global__ void __launch_bounds__(256, 3)
gemm_kernel(const float* __restrict__ rec, const float* __restrict__ wgt)
{
    __shared__ float ws[2][KS * WST];   // [buf][kk][o] transposed w tile
    __shared__ float rs[2][KS * RST];   // [buf][kk][t-dup, interleaved]

    const int tid   = threadIdx.x;
    const int ob    = blockIdx.x;            // 0..1
    const int sp    = blockIdx.y;            // 0..NSPLIT-1
    const int og    = tid >> 3;              // 0..31 (8 o per thread)
    const int tg    = tid & 7;               // 0..7  (4 t per thread)
    const int obase = ob * OTILE;

    const int s_begin = sp * SLAB_BASE + (sp < SLAB_REM ? sp : SLAB_REM);
    const int s_count = SLAB_BASE + (sp < SLAB_REM ? 1 : 0);

    // --- staging index precompute (w: 2 float4 per thread per slab) ---
    // lin bits: [0:5) orow_lo, [5:6) quad, [6:9) orow_hi
    int w_orow[2], w_quad[2];
#pragma unroll
    for (int rep = 0; rep < 2; rep++) {
        int lin = rep * 256 + tid;
        w_orow[rep] = (lin & 31) | ((lin >> 6) << 5);
        w_quad[rep] = (lin >> 5) & 1;
    }
    // rec staging: 1 element per thread: t = tid&31, kk = tid>>5
    const int r_t  = tid & 31;
    const int r_kk = tid >> 5;
    const int r_tg = r_t >> 2;
    const int r_ti = r_t & 3;
    const int r_off = r_kk * RST + (r_ti >> 1) * 32 + r_tg * 4 + (r_ti & 1) * 2;

    unsigned long long acc[16];              // [op][ti]
#pragma unroll
    for (int i = 0; i < 16; i++) acc[i] = 0ULL;

    float4 pw[2];
    float  prv;

    // prologue: load slab 0
    {
        const int kb = s_begin * KS;
#pragma unroll
        for (int rep = 0; rep < 2; rep++)
            pw[rep] = *reinterpret_cast<const float4*>(
                wgt + (size_t)(obase + w_orow[rep]) * KD + kb + w_quad[rep] * 4);
        prv = rec[(size_t)r_t * KD + kb + r_kk];
    }
    {
        // store slab 0 into buf 0
#pragma unroll
        for (int rep = 0; rep < 2; rep++) {
            float* dst = &ws[0][w_quad[rep] * 4 * WST + w_orow[rep]];
            dst[0 * WST] = pw[rep].x;
            dst[1 * WST] = pw[rep].y;
            dst[2 * WST] = pw[rep].z;
            dst[3 * WST] = pw[rep].w;
        }
        *reinterpret_cast<unsigned long long*>(&rs[0][r_off]) = dup2(prv);
    }
    __syncthreads();

    for (int s = 0; s < s_count; s++) {
        const int b = s & 1;
        const bool more = (s + 1 < s_count);
        if (more) {
            const int kb = (s_begin + s + 1) * KS;
#pragma unroll
            for (int rep = 0; rep < 2; rep++)
                pw[rep] = *reinterpret_cast<const float4*>(
                    wgt + (size_t)(obase + w_orow[rep]) * KD + kb + w_quad[rep] * 4);
            prv = rec[(size_t)r_t * KD + kb + r_kk];
        }

        // compute on buf b
#pragma unroll
        for (int kk = 0; kk < KS; kk++) {
            const float* wrow = &ws[b][kk * WST + og * 8];
            const ulonglong2 w01 = *reinterpret_cast<const ulonglong2*>(wrow);
            const ulonglong2 w23 = *reinterpret_cast<const ulonglong2*>(wrow + 4);
            const float* rrow = &rs[b][kk * RST];
            const ulonglong2 rA = *reinterpret_cast<const ulonglong2*>(rrow + tg * 4);
            const ulonglong2 rB = *reinterpret_cast<const ulonglong2*>(rrow + 32 + tg * 4);

            fma2(acc[ 0], w01.x, rA.x); fma2(acc[ 1], w01.x, rA.y);
            fma2(acc[ 2], w01.x, rB.x); fma2(acc[ 3], w01.x, rB.y);
            fma2(acc[ 4], w01.y, rA.x); fma2(acc[ 5], w01.y, rA.y);
            fma2(acc[ 6], w01.y, rB.x); fma2(acc[ 7], w01.y, rB.y);
            fma2(acc[ 8], w23.x, rA.x); fma2(acc[ 9], w23.x, rA.y);
            fma2(acc[10], w23.x, rB.x); fma2(acc[11], w23.x, rB.y);
            fma2(acc[12], w23.y, rA.x); fma2(acc[13], w23.y, rA.y);
            fma2(acc[14], w23.y, rB.x); fma2(acc[15], w23.y, rB.y);
        }

        if (more) {
            const int nb = b ^ 1;
#pragma unroll
            for (int rep = 0; rep < 2; rep++) {
                float* dst = &ws[nb][w_quad[rep] * 4 * WST + w_orow[rep]];
                dst[0 * WST] = pw[rep].x;
                dst[1 * WST] = pw[rep].y;
                dst[2 * WST] = pw[rep].z;
                dst[3 * WST] = pw[rep].w;
            }
            *reinterpret_cast<unsigned long long*>(&rs[nb][r_off]) = dup2(prv);
        }
        __syncthreads();
    }

    // write partials: [sp][t][o]
#pragma unroll
    for (int ti = 0; ti < 4; ti++) {
        const int t = tg * 4 + ti;
        float* dst = g_partial + ((size_t)sp * T_DIM + t) * K2 + obase + og * 8;
        ulonglong2 a; a.x = acc[0 * 4 + ti]; a.y = acc[1 * 4 + ti];
        ulonglong2 c; c.x = acc[2 * 4 + ti]; c.y = acc[3 * 4 + ti];
        *reinterpret_cast<ulonglong2*>(dst)     = a;
        *reinterpret_cast<ulonglong2*>(dst + 4) = c;
    }
}

// ---------------------------------------------------------------------------
// deterministic split-K reduction: g_dot[t][o] = sum_sp partial[sp][t][o]
// ---------------------------------------------------------------------------
__global__ void __launch_bounds__(512) reduce_kernel()
{
    const int t = blockIdx.x;         // 0..31
    const int o = threadIdx.x;        // 0..511
    const size_t base = (size_t)t * K2 + o;
    float s0 = 0.f, s1 = 0.f;
    int sp = 0;
    for (; sp + 2 <= NSPLIT; sp += 2) {
        s0 += g_partial[(size_t)(sp + 0) * T_DIM * K2 + base];
        s1 += g_partial[(size_t)(sp + 1) * T_DIM * K2 + base];
    }
    for (; sp < NSPLIT; sp++)
        s0 += g_partial[(size_t)sp * T_DIM * K2 + base];
    g_dot[t * K2 + o] = s0 + s1;
}

// ---------------------------------------------------------------------------
// post: threshold -> spikes -> first-spike value -> global v -> totals ->
// 8-round first-index argmax k-WTA -> binary output (1 block, 512 threads)
// ---------------------------------------------------------------------------
__global__ void __launch_bounds__(512) post_kernel(float* __restrict__ outp)
{
    const int o = threadIdx.x;        // feature

    unsigned mask = 0;
    int cnt = 0;
#pragma unroll
    for (int t = 0; t < T_DIM; t++) {
        const float v = g_dot[t * K2 + o];
        if (v >= THRESH) { cnt++; mask |= (1u << t); }
    }
    int first = T_DIM - cnt;
    if (first > T_DIM - 1) first = T_DIM - 1;
    const float fv    = g_dot[first * K2 + o];
    const float value = (fv < THRESH) ? 0.0f : fv;
    const float cand  = (cnt > 0) ? value : 0.0f;

    __shared__ float sm[K2];
    sm[o] = cand;
    __syncthreads();
    for (int s = K2 / 2; s > 0; s >>= 1) {
        if (o < s) sm[o] = fmaxf(sm[o], sm[o + s]);
        __syncthreads();
    }
    const float voff = sm[0] * (float)T_DIM;
    __syncthreads();

    __shared__ float tots[K2];
    __shared__ unsigned long long pk[K2];
    __shared__ unsigned char sel[K2];
    tots[o] = (cnt > 0) ? (float)cnt * (value + voff) : 0.0f;
    sel[o]  = 0;
    __syncthreads();

    for (int r = 0; r < 8; r++) {
        pk[o] = ((unsigned long long)__float_as_uint(tots[o]) << 32)
                | (unsigned)(K2 - 1 - o);          // smaller idx wins ties
        __syncthreads();
        for (int s = K2 / 2; s > 0; s >>= 1) {
            if (o < s) { unsigned long long b = pk[o + s]; if (b > pk[o]) pk[o] = b; }
            __syncthreads();
        }
        if (o == 0) {
            const int idx = (K2 - 1) - (int)(unsigned)(pk[0] & 0xffffffffULL);
            if (tots[idx] != 0.0f) sel[idx] = 1;
            tots[idx] = 0.0f;
        }
        __syncthreads();
    }

#pragma unroll
    for (int t = 0; t < T_DIM; t++) {
        outp[t * K2 + o] = (sel[o] && ((mask >> t) & 1u)) ? 1.0f : 0.0f;
    }
}

// ---------------------------------------------------------------------------
extern "C" void kernel_launch(void* const* d_in, const int* in_sizes, int n_in,
                              void* d_out, int out_size)
{
    const float* rec = (const float*)d_in[0];   // (32,1,64,4096)
    const float* wgt = (const float*)d_in[1];   // (512,1,64,4096)
    if (n_in >= 2 && in_sizes[0] > in_sizes[1]) {
        const float* tmp = rec; rec = wgt; wgt = tmp;
    }
    float* outp = (float*)d_out;

    gemm_kernel<<<dim3(2, NSPLIT), 256>>>(rec, wgt);
    reduce_kernel<<<T_DIM, K2>>>();
    post_kernel<<<1, K2>>>(outp);
}